// round 6
// baseline (speedup 1.0000x reference)
#include <cuda_runtime.h>
#include <cuda_bf16.h>
#include <math.h>

// Problem constants
#define B_    8
#define N_    128
#define K_    16
#define ALPHA 0.01f
#define LAM   1.0f
#define KAPPA 1.0f
#define EPS   1e-6f

#define NODES (B_ * N_)   // 1024
#define STR   20          // shared column stride (floats)
#define IPB   2           // i-rows per block in pair_kernel

// Scratch (device globals — no allocation allowed)
// M_g layout per node: [l4][k][c] so float4 idx (node*64 + l4*16 + k) is lane-coalesced.
__device__ __align__(16) float E_g[NODES * K_ * K_];
__device__ __align__(16) float M_g[NODES * K_ * K_];
__device__ __align__(16) float u_g[NODES * K_];

// load a 16-float column (col-major, stride STR, 16B aligned) as 4x float4
#define LOADCOL(dst, base)                                            \
    {   const float4* _p = (const float4*)(base);                     \
        float4 _v0 = _p[0], _v1 = _p[1], _v2 = _p[2], _v3 = _p[3];    \
        dst[0]=_v0.x; dst[1]=_v0.y; dst[2]=_v0.z; dst[3]=_v0.w;       \
        dst[4]=_v1.x; dst[5]=_v1.y; dst[6]=_v1.z; dst[7]=_v1.w;       \
        dst[8]=_v2.x; dst[9]=_v2.y; dst[10]=_v2.z; dst[11]=_v2.w;     \
        dst[12]=_v3.x; dst[13]=_v3.y; dst[14]=_v3.z; dst[15]=_v3.w; }

// ---------------------------------------------------------------------------
// Kernel 1: per-node precompute.  E = expm(A), A = phi.G (antisymmetric)
// exp(A) = Pe(A2) + A*Po(A2), Taylor-9, scaling/squaring theta=1.0.
// (unchanged from R5 — it improved to ~9us)
// ---------------------------------------------------------------------------
__global__ __launch_bounds__(256)
void prep_kernel(const float* __restrict__ mu_q,
                 const float* __restrict__ sigma_q,
                 const float* __restrict__ phi,
                 const float* __restrict__ gen)
{
    const int node = blockIdx.x;
    const int tid  = threadIdx.x;          // 0..255
    const int r = tid >> 4, c = tid & 15;

    __shared__ __align__(16) float Acm [16 * STR];   // A (scaled)
    __shared__ __align__(16) float Bcm [16 * STR];   // A2
    __shared__ __align__(16) float Ccm [16 * STR];   // A4
    __shared__ __align__(16) float Xcm [16 * STR];   // temp / ping
    __shared__ __align__(16) float Ycm [16 * STR];   // temp / pong
    __shared__ float rowsum[16];
    __shared__ float dinv[16];
    __shared__ float mush[16];

    const float p0 = __ldg(&phi[node*3 + 0]);
    const float p1 = __ldg(&phi[node*3 + 1]);
    const float p2 = __ldg(&phi[node*3 + 2]);
    const float a_raw = p0 * __ldg(&gen[tid])
                      + p1 * __ldg(&gen[256 + tid])
                      + p2 * __ldg(&gen[512 + tid]);

    // row inf-norm via half-warp shfl over c
    {
        float ab = fabsf(a_raw);
        ab += __shfl_xor_sync(0xffffffffu, ab, 8);
        ab += __shfl_xor_sync(0xffffffffu, ab, 4);
        ab += __shfl_xor_sync(0xffffffffu, ab, 2);
        ab += __shfl_xor_sync(0xffffffffu, ab, 1);
        if (c == 0) rowsum[r] = ab;
    }
    if (tid < 16) {
        const float sq = fmaxf(__ldg(&sigma_q[node*16 + tid]), EPS);
        dinv[tid] = 1.0f / (sq + EPS);
        mush[tid] = __ldg(&mu_q[node*16 + tid]);
    }
    __syncthreads();

    int s_sq;
    {
        float nrm = 0.f;
        #pragma unroll
        for (int l = 0; l < 16; l++) nrm = fmaxf(nrm, rowsum[l]);
        int s = 0;
        while (nrm > 1.0f && s < 30) { nrm *= 0.5f; s++; }
        s_sq = s;
    }
    Acm[c*STR + r] = a_raw * ldexpf(1.0f, -s_sq);
    __syncthreads();

    // ---- A2 = A*A ----
    {
        float row[16], col[16];
        #pragma unroll
        for (int l = 0; l < 16; l++) row[l] = Acm[l*STR + r];
        LOADCOL(col, Acm + c*STR);
        float acc = 0.f;
        #pragma unroll
        for (int l = 0; l < 16; l++) acc = fmaf(row[l], col[l], acc);
        Bcm[c*STR + r] = acc;
    }
    __syncthreads();

    // ---- A4 = A2*A2 ----
    {
        float row[16], col[16];
        #pragma unroll
        for (int l = 0; l < 16; l++) row[l] = Bcm[l*STR + r];
        LOADCOL(col, Bcm + c*STR);
        float acc = 0.f;
        #pragma unroll
        for (int l = 0; l < 16; l++) acc = fmaf(row[l], col[l], acc);
        Ccm[c*STR + r] = acc;
    }
    __syncthreads();

    // ---- tails folded ----
    float even;
    {
        float row[16], colA2[16], colA4[16];
        #pragma unroll
        for (int l = 0; l < 16; l++) row[l] = Ccm[l*STR + r];
        LOADCOL(colA2, Bcm + c*STR);
        LOADCOL(colA4, Ccm + c*STR);
        float t_we = 0.f, t_wo = 0.f;
        #pragma unroll
        for (int l = 0; l < 16; l++) {
            t_we = fmaf(row[l], fmaf(colA2[l], 1.0f/720.0f,  colA4[l] * (1.0f/40320.0f)),  t_we);
            t_wo = fmaf(row[l], fmaf(colA2[l], 1.0f/5040.0f, colA4[l] * (1.0f/362880.0f)), t_wo);
        }
        const float A2rc = Bcm[c*STR + r];
        const float A4rc = Ccm[c*STR + r];
        const float idn  = (r == c) ? 1.0f : 0.0f;
        even = idn + 0.5f        * A2rc + (1.0f/24.0f)  * A4rc + t_we;
        Xcm[c*STR + r] = idn + (1.0f/6.0f) * A2rc + (1.0f/120.0f) * A4rc + t_wo;
    }
    __syncthreads();

    // ---- E = even + A * odd  -> Ycm ----
    {
        float row[16], col[16];
        #pragma unroll
        for (int l = 0; l < 16; l++) row[l] = Acm[l*STR + r];
        LOADCOL(col, Xcm + c*STR);
        float acc = even;
        #pragma unroll
        for (int l = 0; l < 16; l++) acc = fmaf(row[l], col[l], acc);
        Ycm[c*STR + r] = acc;
    }
    __syncthreads();

    // ---- squarings ----
    float* Xp = Ycm;
    float* Yp = Xcm;
    for (int t = 0; t < s_sq; t++) {
        float row[16], col[16];
        #pragma unroll
        for (int l = 0; l < 16; l++) row[l] = Xp[l*STR + r];
        LOADCOL(col, Xp + c*STR);
        float s = 0.f;
        #pragma unroll
        for (int l = 0; l < 16; l++) s = fmaf(row[l], col[l], s);
        Yp[c*STR + r] = s;
        __syncthreads();
        float* tmp = Xp; Xp = Yp; Yp = tmp;
    }
    // Xp holds E, column-major.

    // ---- M[r][c] = sum_l E[l][r] dinv[l] E[l][c] ----
    {
        float rowd[16], col[16];
        LOADCOL(rowd, Xp + r*STR);
        #pragma unroll
        for (int l = 0; l < 16; l++) rowd[l] *= dinv[l];
        LOADCOL(col, Xp + c*STR);
        float m = 0.f;
        #pragma unroll
        for (int l = 0; l < 16; l++) m = fmaf(rowd[l], col[l], m);
        M_g[node*256 + (c >> 2)*64 + r*4 + (c & 3)] = m;
        E_g[node*256 + r*16 + c] = Xp[c*STR + r];
    }
    if (tid < 16) {
        float uu = 0.f;
        #pragma unroll
        for (int l = 0; l < 16; l++) uu = fmaf(Xp[tid*STR + l], mush[l], uu);
        u_g[node*16 + tid] = uu;
    }
}

// ---------------------------------------------------------------------------
// Kernel 2: pair reduction. IPB=2 i-rows per block, 256 threads = 16
// half-warps (j 16-wide per iteration, 8 iterations). Grid = 512 blocks.
// Per j:  t_j = M_j u_j (once);  per i:  a = M_j u_i,  v = a - t_j,
//         kl = 0.5 w.v (shfl-16),  accumulate S1/S2/s3.
// ---------------------------------------------------------------------------
__global__ __launch_bounds__(256, 3)
void pair_kernel(const float* __restrict__ mu_q,
                 const float* __restrict__ sigma_q,
                 const float* __restrict__ mu_p,
                 const float* __restrict__ sigma_p,
                 const float* __restrict__ beta,
                 float* __restrict__ out)
{
    const int blk = blockIdx.x;        // 0..511
    const int b   = blk >> 6;          // 64 blocks per batch
    const int i0  = (blk & 63) * IPB;
    const int tid = threadIdx.x;       // 0..255

    __shared__ __align__(16) float u_sh[N_ * K_];     // 8 KB
    __shared__ float beta_sh[IPB][N_];
    __shared__ float red1[IPB][16][16];
    __shared__ float red2[IPB][16][16];
    __shared__ float red3[IPB][16];
    __shared__ float t_sh[IPB][16];

    float4* u_sh4 = (float4*)u_sh;
    const float4* ub4 = (const float4*)(u_g + b * N_ * K_);
    #pragma unroll
    for (int idx = tid; idx < N_ * K_ / 4; idx += 256) u_sh4[idx] = ub4[idx];
    // 256 threads load 2 beta rows of 128
    beta_sh[tid >> 7][tid & 127] = __ldg(&beta[(b * N_ + i0 + (tid >> 7)) * N_ + (tid & 127)]);
    __syncthreads();

    const int k  = tid & 15;           // component / row
    const int hw = tid >> 4;           // half-warp id 0..15

    // cache the IPB u_i vectors in registers (all static indices)
    float uir[IPB][16];
    float uik[IPB];
    #pragma unroll
    for (int ii = 0; ii < IPB; ii++) {
        const float4* p = (const float4*)(u_sh + (i0 + ii) * 16);
        float4 v0 = p[0], v1 = p[1], v2 = p[2], v3 = p[3];
        uir[ii][0]=v0.x;  uir[ii][1]=v0.y;  uir[ii][2]=v0.z;  uir[ii][3]=v0.w;
        uir[ii][4]=v1.x;  uir[ii][5]=v1.y;  uir[ii][6]=v1.z;  uir[ii][7]=v1.w;
        uir[ii][8]=v2.x;  uir[ii][9]=v2.y;  uir[ii][10]=v2.z; uir[ii][11]=v2.w;
        uir[ii][12]=v3.x; uir[ii][13]=v3.y; uir[ii][14]=v3.z; uir[ii][15]=v3.w;
        uik[ii] = u_sh[(i0 + ii) * 16 + k];
    }

    float s1[IPB], s2[IPB], s3[IPB];
    #pragma unroll
    for (int ii = 0; ii < IPB; ii++) { s1[ii]=0.f; s2[ii]=0.f; s3[ii]=0.f; }

    const float4* Mb4 = (const float4*)(M_g + b * N_ * 256);

    #pragma unroll 2
    for (int iter = 0; iter < 8; iter++) {
        const int j = iter * 16 + hw;
        const float4* Mj = Mb4 + j * 64;

        const float4 m0 = __ldg(&Mj[ 0 + k]);
        const float4 m1 = __ldg(&Mj[16 + k]);
        const float4 m2 = __ldg(&Mj[32 + k]);
        const float4 m3 = __ldg(&Mj[48 + k]);

        const float4* up = (const float4*)(u_sh + j * 16);
        const float4 uj0 = up[0], uj1 = up[1], uj2 = up[2], uj3 = up[3];
        const float  ujk = u_sh[j * 16 + k];

        // t_j[k] = M_j[k][:] . u_j
        float tj = m0.x * uj0.x;
        tj = fmaf(m0.y, uj0.y, tj); tj = fmaf(m0.z, uj0.z, tj); tj = fmaf(m0.w, uj0.w, tj);
        tj = fmaf(m1.x, uj1.x, tj); tj = fmaf(m1.y, uj1.y, tj); tj = fmaf(m1.z, uj1.z, tj); tj = fmaf(m1.w, uj1.w, tj);
        tj = fmaf(m2.x, uj2.x, tj); tj = fmaf(m2.y, uj2.y, tj); tj = fmaf(m2.z, uj2.z, tj); tj = fmaf(m2.w, uj2.w, tj);
        tj = fmaf(m3.x, uj3.x, tj); tj = fmaf(m3.y, uj3.y, tj); tj = fmaf(m3.z, uj3.z, tj); tj = fmaf(m3.w, uj3.w, tj);

        #pragma unroll
        for (int ii = 0; ii < IPB; ii++) {
            float a = m0.x * uir[ii][0];
            a = fmaf(m0.y, uir[ii][1],  a); a = fmaf(m0.z, uir[ii][2],  a); a = fmaf(m0.w, uir[ii][3],  a);
            a = fmaf(m1.x, uir[ii][4],  a); a = fmaf(m1.y, uir[ii][5],  a); a = fmaf(m1.z, uir[ii][6],  a); a = fmaf(m1.w, uir[ii][7],  a);
            a = fmaf(m2.x, uir[ii][8],  a); a = fmaf(m2.y, uir[ii][9],  a); a = fmaf(m2.z, uir[ii][10], a); a = fmaf(m2.w, uir[ii][11], a);
            a = fmaf(m3.x, uir[ii][12], a); a = fmaf(m3.y, uir[ii][13], a); a = fmaf(m3.z, uir[ii][14], a); a = fmaf(m3.w, uir[ii][15], a);

            const float v = a - tj;
            const float w = uik[ii] - ujk;
            float p = w * v;
            p += __shfl_xor_sync(0xffffffffu, p, 8);
            p += __shfl_xor_sync(0xffffffffu, p, 4);
            p += __shfl_xor_sync(0xffffffffu, p, 2);
            p += __shfl_xor_sync(0xffffffffu, p, 1);
            const float kl = 0.5f * p;

            const float bj  = beta_sh[ii][j];
            const float bkl = bj * kl;
            s1[ii] = fmaf(bj,  v, s1[ii]);
            s2[ii] = fmaf(bkl, v, s2[ii]);
            s3[ii] += bkl;
        }
    }

    #pragma unroll
    for (int ii = 0; ii < IPB; ii++) {
        red1[ii][hw][k] = s1[ii];
        red2[ii][hw][k] = s2[ii];
        if (k == 0) red3[ii][hw] = s3[ii];
    }
    __syncthreads();

    if (tid < 16 * IPB) {
        const int ii = tid >> 4, kk = tid & 15;
        float S1 = 0.f, S2 = 0.f, S3 = 0.f;
        #pragma unroll
        for (int h = 0; h < 16; h++) {
            S1 += red1[ii][h][kk];
            S2 += red2[ii][h][kk];
            S3 += red3[ii][h];
        }
        t_sh[ii][kk] = LAM * S1 + (LAM / KAPPA) * (S2 - S3 * S1);
    }
    __syncthreads();

    if (tid < 16 * IPB) {
        const int ii = tid >> 4, kk = tid & 15;
        const int node = b * N_ + i0 + ii;
        const float* Ei = E_g + node * 256;
        float g = 0.f;
        #pragma unroll
        for (int l = 0; l < 16; l++) g = fmaf(Ei[kk*16 + l], t_sh[ii][l], g);

        const float sp = fmaxf(__ldg(&sigma_p[node*16 + kk]), EPS);
        const float sq = fmaxf(__ldg(&sigma_q[node*16 + kk]), EPS);
        const float dm = __ldg(&mu_q[node*16 + kk]) - __ldg(&mu_p[node*16 + kk]);

        out[node*16 + kk]            = g + ALPHA * dm / sp;
        out[NODES*K_ + node*16 + kk] = ALPHA * 0.5f * (1.0f / sp - 1.0f / sq);
    }
}

extern "C" void kernel_launch(void* const* d_in, const int* in_sizes, int n_in,
                              void* d_out, int out_size)
{
    const float* mu_q    = (const float*)d_in[0];
    const float* sigma_q = (const float*)d_in[1];
    const float* mu_p    = (const float*)d_in[2];
    const float* sigma_p = (const float*)d_in[3];
    const float* beta    = (const float*)d_in[4];
    const float* phi     = (const float*)d_in[5];
    const float* gen     = (const float*)d_in[6];
    float* out = (float*)d_out;

    prep_kernel<<<NODES, 256>>>(mu_q, sigma_q, phi, gen);
    pair_kernel<<<NODES / IPB, 256>>>(mu_q, sigma_q, mu_p, sigma_p, beta, out);
}

// round 7
// speedup vs baseline: 1.1456x; 1.1456x over previous
#include <cuda_runtime.h>
#include <cuda_bf16.h>
#include <math.h>

// Problem constants
#define B_    8
#define N_    128
#define K_    16
#define ALPHA 0.01f
#define LAM   1.0f
#define KAPPA 1.0f
#define EPS   1e-6f

#define NODES (B_ * N_)   // 1024
#define WPB   4           // warps (nodes) per block in prep

// Scratch (device globals — no allocation allowed)
// M_g layout per node: [l4][k][c] so float4 idx (node*64 + l4*16 + k) is lane-coalesced.
__device__ __align__(16) float E_g[NODES * K_ * K_];
__device__ __align__(16) float M_g[NODES * K_ * K_];
__device__ __align__(16) float u_g[NODES * K_];

// ---------------------------------------------------------------------------
// Warp-cooperative 16x16 matmul: D = S1 * S2 (+ acc init), row-major smem.
// Lane owns row r = lane>>1, cols cb..cb+7 (cb = (lane&1)*8).
// No aliasing between D and S1/S2 allowed. Ends with __syncwarp().
// ---------------------------------------------------------------------------
__device__ __forceinline__ void warp_mm(const float* __restrict__ S1,
                                        const float* __restrict__ S2,
                                        float* __restrict__ D,
                                        int r, int cb, float* acc)
{
    float row[16];
    {
        const float4* rp = (const float4*)(S1 + r * 16);
        float4 r0 = rp[0], r1 = rp[1], r2 = rp[2], r3 = rp[3];
        row[0]=r0.x; row[1]=r0.y; row[2]=r0.z; row[3]=r0.w;
        row[4]=r1.x; row[5]=r1.y; row[6]=r1.z; row[7]=r1.w;
        row[8]=r2.x; row[9]=r2.y; row[10]=r2.z; row[11]=r2.w;
        row[12]=r3.x; row[13]=r3.y; row[14]=r3.z; row[15]=r3.w;
    }
    #pragma unroll
    for (int l = 0; l < 16; l++) {
        const float4 b0 = *(const float4*)(S2 + l*16 + cb);
        const float4 b1 = *(const float4*)(S2 + l*16 + cb + 4);
        acc[0] = fmaf(row[l], b0.x, acc[0]);
        acc[1] = fmaf(row[l], b0.y, acc[1]);
        acc[2] = fmaf(row[l], b0.z, acc[2]);
        acc[3] = fmaf(row[l], b0.w, acc[3]);
        acc[4] = fmaf(row[l], b1.x, acc[4]);
        acc[5] = fmaf(row[l], b1.y, acc[5]);
        acc[6] = fmaf(row[l], b1.z, acc[6]);
        acc[7] = fmaf(row[l], b1.w, acc[7]);
    }
    *(float4*)(D + r*16 + cb)     = make_float4(acc[0], acc[1], acc[2], acc[3]);
    *(float4*)(D + r*16 + cb + 4) = make_float4(acc[4], acc[5], acc[6], acc[7]);
    __syncwarp();
}

// ---------------------------------------------------------------------------
// Kernel 1: warp-per-node expm precompute (no block barriers).
// E = exp(A), A = phi.G antisymmetric; exp(A) = Pe(A2) + A*Po(A2), Taylor-9,
// scaling/squaring theta=1.0 (inf-norm via warp shfl).
// Outputs E, M = E^T D^{-1} E (permuted layout), u = E^T mu.
// ---------------------------------------------------------------------------
__global__ __launch_bounds__(128)
void prep_kernel(const float* __restrict__ mu_q,
                 const float* __restrict__ sigma_q,
                 const float* __restrict__ phi,
                 const float* __restrict__ gen)
{
    const int lane = threadIdx.x & 31;
    const int wrp  = threadIdx.x >> 5;
    const int node = blockIdx.x * WPB + wrp;
    const int r    = lane >> 1;
    const int cb   = (lane & 1) * 8;

    __shared__ __align__(16) float sm[WPB * 800];
    float* P0 = sm + wrp * 800;     // A
    float* P1 = P0 + 256;           // slot 1
    float* P2 = P0 + 512;           // slot 2
    float* dv = P0 + 768;           // dinv[16]
    float* mh = P0 + 784;           // mu[16]

    // ---- build A: a[e] = sum_a phi[a] * G[a][r][cb+e] ----
    const float q0 = __ldg(&phi[node*3 + 0]);
    const float q1 = __ldg(&phi[node*3 + 1]);
    const float q2 = __ldg(&phi[node*3 + 2]);
    const int gi = r * 16 + cb;
    float a[8];
    {
        const float4 g00 = __ldg((const float4*)(gen + gi));
        const float4 g01 = __ldg((const float4*)(gen + gi + 4));
        const float4 g10 = __ldg((const float4*)(gen + 256 + gi));
        const float4 g11 = __ldg((const float4*)(gen + 256 + gi + 4));
        const float4 g20 = __ldg((const float4*)(gen + 512 + gi));
        const float4 g21 = __ldg((const float4*)(gen + 512 + gi + 4));
        a[0] = q0*g00.x + q1*g10.x + q2*g20.x;
        a[1] = q0*g00.y + q1*g10.y + q2*g20.y;
        a[2] = q0*g00.z + q1*g10.z + q2*g20.z;
        a[3] = q0*g00.w + q1*g10.w + q2*g20.w;
        a[4] = q0*g01.x + q1*g11.x + q2*g21.x;
        a[5] = q0*g01.y + q1*g11.y + q2*g21.y;
        a[6] = q0*g01.z + q1*g11.z + q2*g21.z;
        a[7] = q0*g01.w + q1*g11.w + q2*g21.w;
    }

    // ---- inf-norm via shfl (rowsum across half-row pair, max across rows) ----
    float s = fabsf(a[0]) + fabsf(a[1]) + fabsf(a[2]) + fabsf(a[3])
            + fabsf(a[4]) + fabsf(a[5]) + fabsf(a[6]) + fabsf(a[7]);
    s += __shfl_xor_sync(0xffffffffu, s, 1);     // full row sum
    float mx = s;
    mx = fmaxf(mx, __shfl_xor_sync(0xffffffffu, mx, 2));
    mx = fmaxf(mx, __shfl_xor_sync(0xffffffffu, mx, 4));
    mx = fmaxf(mx, __shfl_xor_sync(0xffffffffu, mx, 8));
    mx = fmaxf(mx, __shfl_xor_sync(0xffffffffu, mx, 16));
    int s_sq = 0;
    while (mx > 1.0f && s_sq < 30) { mx *= 0.5f; s_sq++; }
    const float sc = ldexpf(1.0f, -s_sq);
    #pragma unroll
    for (int e = 0; e < 8; e++) a[e] *= sc;
    *(float4*)(P0 + r*16 + cb)     = make_float4(a[0], a[1], a[2], a[3]);
    *(float4*)(P0 + r*16 + cb + 4) = make_float4(a[4], a[5], a[6], a[7]);
    if (lane < 16) {
        const float sq = fmaxf(__ldg(&sigma_q[node*16 + lane]), EPS);
        dv[lane] = 1.0f / (sq + EPS);
        mh[lane] = __ldg(&mu_q[node*16 + lane]);
    }
    __syncwarp();

    // ---- A2 = A*A -> P1 ----
    float a2own[8] = {0,0,0,0,0,0,0,0};
    warp_mm(P0, P0, P1, r, cb, a2own);

    // ---- A4 = A2*A2 -> P2 ----
    float a4own[8] = {0,0,0,0,0,0,0,0};
    warp_mm(P1, P1, P2, r, cb, a4own);

    // ---- tails: S2e = A4row . A2cols, S4e = A4row . A4cols ----
    float even[8], odd[8];
    {
        float row[16];
        {
            const float4* rp = (const float4*)(P2 + r * 16);
            float4 r0 = rp[0], r1 = rp[1], r2 = rp[2], r3 = rp[3];
            row[0]=r0.x; row[1]=r0.y; row[2]=r0.z; row[3]=r0.w;
            row[4]=r1.x; row[5]=r1.y; row[6]=r1.z; row[7]=r1.w;
            row[8]=r2.x; row[9]=r2.y; row[10]=r2.z; row[11]=r2.w;
            row[12]=r3.x; row[13]=r3.y; row[14]=r3.z; row[15]=r3.w;
        }
        float S2e[8] = {0,0,0,0,0,0,0,0};
        float S4e[8] = {0,0,0,0,0,0,0,0};
        #pragma unroll
        for (int l = 0; l < 16; l++) {
            const float4 b0 = *(const float4*)(P1 + l*16 + cb);
            const float4 b1 = *(const float4*)(P1 + l*16 + cb + 4);
            const float4 d0 = *(const float4*)(P2 + l*16 + cb);
            const float4 d1 = *(const float4*)(P2 + l*16 + cb + 4);
            S2e[0]=fmaf(row[l],b0.x,S2e[0]); S2e[1]=fmaf(row[l],b0.y,S2e[1]);
            S2e[2]=fmaf(row[l],b0.z,S2e[2]); S2e[3]=fmaf(row[l],b0.w,S2e[3]);
            S2e[4]=fmaf(row[l],b1.x,S2e[4]); S2e[5]=fmaf(row[l],b1.y,S2e[5]);
            S2e[6]=fmaf(row[l],b1.z,S2e[6]); S2e[7]=fmaf(row[l],b1.w,S2e[7]);
            S4e[0]=fmaf(row[l],d0.x,S4e[0]); S4e[1]=fmaf(row[l],d0.y,S4e[1]);
            S4e[2]=fmaf(row[l],d0.z,S4e[2]); S4e[3]=fmaf(row[l],d0.w,S4e[3]);
            S4e[4]=fmaf(row[l],d1.x,S4e[4]); S4e[5]=fmaf(row[l],d1.y,S4e[5]);
            S4e[6]=fmaf(row[l],d1.z,S4e[6]); S4e[7]=fmaf(row[l],d1.w,S4e[7]);
        }
        #pragma unroll
        for (int e = 0; e < 8; e++) {
            const float idn = (r == cb + e) ? 1.0f : 0.0f;
            even[e] = idn + 0.5f        * a2own[e] + (1.0f/24.0f)  * a4own[e]
                          + (1.0f/720.0f)  * S2e[e] + (1.0f/40320.0f)  * S4e[e];
            odd[e]  = idn + (1.0f/6.0f) * a2own[e] + (1.0f/120.0f) * a4own[e]
                          + (1.0f/5040.0f) * S2e[e] + (1.0f/362880.0f) * S4e[e];
        }
    }
    __syncwarp();   // all reads of P1 (A2) done
    *(float4*)(P1 + r*16 + cb)     = make_float4(odd[0], odd[1], odd[2], odd[3]);
    *(float4*)(P1 + r*16 + cb + 4) = make_float4(odd[4], odd[5], odd[6], odd[7]);
    __syncwarp();

    // ---- E = even + A * odd -> P2 ----
    warp_mm(P0, P1, P2, r, cb, even);   // even[] is the accumulator init

    // ---- squarings (ping-pong P2 <-> P1) ----
    float* Xp = P2;
    float* Yp = P1;
    for (int t = 0; t < s_sq; t++) {
        float acc[8] = {0,0,0,0,0,0,0,0};
        warp_mm(Xp, Xp, Yp, r, cb, acc);
        float* tmp = Xp; Xp = Yp; Yp = tmp;
    }
    // Xp holds E (row-major).

    // ---- M[r][cb+e] = sum_l E[l][r] dinv[l] E[l][cb+e] ----
    {
        float colr[16];
        #pragma unroll
        for (int l = 0; l < 16; l++) colr[l] = Xp[l*16 + r] * dv[l];
        float m[8] = {0,0,0,0,0,0,0,0};
        #pragma unroll
        for (int l = 0; l < 16; l++) {
            const float4 e0 = *(const float4*)(Xp + l*16 + cb);
            const float4 e1 = *(const float4*)(Xp + l*16 + cb + 4);
            m[0]=fmaf(colr[l],e0.x,m[0]); m[1]=fmaf(colr[l],e0.y,m[1]);
            m[2]=fmaf(colr[l],e0.z,m[2]); m[3]=fmaf(colr[l],e0.w,m[3]);
            m[4]=fmaf(colr[l],e1.x,m[4]); m[5]=fmaf(colr[l],e1.y,m[5]);
            m[6]=fmaf(colr[l],e1.z,m[6]); m[7]=fmaf(colr[l],e1.w,m[7]);
        }
        // permuted store: chunk l4 = cb/4 and cb/4+1, contiguous 4 floats at r*4
        float* Md = M_g + node*256;
        *(float4*)(Md + (cb >> 2)*64       + r*4) = make_float4(m[0], m[1], m[2], m[3]);
        *(float4*)(Md + ((cb >> 2) + 1)*64 + r*4) = make_float4(m[4], m[5], m[6], m[7]);
        // E store (row-major): own row
        const float4 e0 = *(const float4*)(Xp + r*16 + cb);
        const float4 e1 = *(const float4*)(Xp + r*16 + cb + 4);
        *(float4*)(E_g + node*256 + r*16 + cb)     = e0;
        *(float4*)(E_g + node*256 + r*16 + cb + 4) = e1;
    }
    // ---- u[k] = col k of E . mu ----
    if (lane < 16) {
        float uu = 0.f;
        #pragma unroll
        for (int l = 0; l < 16; l++) uu = fmaf(Xp[l*16 + lane], mh[l], uu);
        u_g[node*16 + lane] = uu;
    }
}

// ---------------------------------------------------------------------------
// Kernel 2: pair reduction. One block per (b,i): 256 threads = 16 half-warps,
// 8 iterations over j. Grid = 1024 blocks, 4 blocks/SM (regs<=64).
// ---------------------------------------------------------------------------
__global__ __launch_bounds__(256, 4)
void pair_kernel(const float* __restrict__ mu_q,
                 const float* __restrict__ sigma_q,
                 const float* __restrict__ mu_p,
                 const float* __restrict__ sigma_p,
                 const float* __restrict__ beta,
                 float* __restrict__ out)
{
    const int blk = blockIdx.x;        // 0..1023
    const int b   = blk >> 7;
    const int i   = blk & 127;
    const int tid = threadIdx.x;       // 0..255

    __shared__ __align__(16) float u_sh[N_ * K_];     // 8 KB
    __shared__ float beta_sh[N_];
    __shared__ float red1[16][16];
    __shared__ float red2[16][16];
    __shared__ float red3[16];
    __shared__ float t_sh[16];

    float4* u_sh4 = (float4*)u_sh;
    const float4* ub4 = (const float4*)(u_g + b * N_ * K_);
    #pragma unroll
    for (int idx = tid; idx < N_ * K_ / 4; idx += 256) u_sh4[idx] = ub4[idx];
    if (tid < N_) beta_sh[tid] = __ldg(&beta[(b * N_ + i) * N_ + tid]);
    __syncthreads();

    const int k  = tid & 15;           // component / row
    const int hw = tid >> 4;           // half-warp id 0..15

    const float4 ui0 = u_sh4[i*4 + 0];
    const float4 ui1 = u_sh4[i*4 + 1];
    const float4 ui2 = u_sh4[i*4 + 2];
    const float4 ui3 = u_sh4[i*4 + 3];
    const float  ui_k = u_sh[i*16 + k];

    float s1 = 0.f, s2 = 0.f, s3 = 0.f;
    const float4* Mb4 = (const float4*)(M_g + b * N_ * 256);

    #pragma unroll 2
    for (int iter = 0; iter < 8; iter++) {
        const int j = iter * 16 + hw;
        const float4* Mj = Mb4 + j * 64;

        const float4 m0 = __ldg(&Mj[ 0 + k]);
        const float4 m1 = __ldg(&Mj[16 + k]);
        const float4 m2 = __ldg(&Mj[32 + k]);
        const float4 m3 = __ldg(&Mj[48 + k]);

        const float4* up = (const float4*)(u_sh + j * 16);
        const float4 uj0 = up[0], uj1 = up[1], uj2 = up[2], uj3 = up[3];

        float4 w0, w1, w2, w3;
        w0.x = ui0.x - uj0.x; w0.y = ui0.y - uj0.y; w0.z = ui0.z - uj0.z; w0.w = ui0.w - uj0.w;
        w1.x = ui1.x - uj1.x; w1.y = ui1.y - uj1.y; w1.z = ui1.z - uj1.z; w1.w = ui1.w - uj1.w;
        w2.x = ui2.x - uj2.x; w2.y = ui2.y - uj2.y; w2.z = ui2.z - uj2.z; w2.w = ui2.w - uj2.w;
        w3.x = ui3.x - uj3.x; w3.y = ui3.y - uj3.y; w3.z = ui3.z - uj3.z; w3.w = ui3.w - uj3.w;

        float v = m0.x * w0.x;
        v = fmaf(m0.y, w0.y, v); v = fmaf(m0.z, w0.z, v); v = fmaf(m0.w, w0.w, v);
        v = fmaf(m1.x, w1.x, v); v = fmaf(m1.y, w1.y, v); v = fmaf(m1.z, w1.z, v); v = fmaf(m1.w, w1.w, v);
        v = fmaf(m2.x, w2.x, v); v = fmaf(m2.y, w2.y, v); v = fmaf(m2.z, w2.z, v); v = fmaf(m2.w, w2.w, v);
        v = fmaf(m3.x, w3.x, v); v = fmaf(m3.y, w3.y, v); v = fmaf(m3.z, w3.z, v); v = fmaf(m3.w, w3.w, v);

        const float wk = ui_k - u_sh[j*16 + k];
        float p = wk * v;
        p += __shfl_xor_sync(0xffffffffu, p, 8);
        p += __shfl_xor_sync(0xffffffffu, p, 4);
        p += __shfl_xor_sync(0xffffffffu, p, 2);
        p += __shfl_xor_sync(0xffffffffu, p, 1);
        const float kl = 0.5f * p;

        const float bj  = beta_sh[j];
        const float bkl = bj * kl;
        s1 = fmaf(bj,  v, s1);
        s2 = fmaf(bkl, v, s2);
        s3 += bkl;
    }

    red1[hw][k] = s1;
    red2[hw][k] = s2;
    if (k == 0) red3[hw] = s3;
    __syncthreads();

    if (tid < 16) {
        float S1 = 0.f, S2 = 0.f, S3 = 0.f;
        #pragma unroll
        for (int h = 0; h < 16; h++) {
            S1 += red1[h][tid];
            S2 += red2[h][tid];
            S3 += red3[h];
        }
        t_sh[tid] = LAM * S1 + (LAM / KAPPA) * (S2 - S3 * S1);
    }
    __syncthreads();

    if (tid < 16) {
        const int node = b * N_ + i;
        const float* Ei = E_g + node * 256;
        float g = 0.f;
        #pragma unroll
        for (int l = 0; l < 16; l++) g = fmaf(Ei[tid*16 + l], t_sh[l], g);

        const float sp = fmaxf(__ldg(&sigma_p[node*16 + tid]), EPS);
        const float sq = fmaxf(__ldg(&sigma_q[node*16 + tid]), EPS);
        const float dm = __ldg(&mu_q[node*16 + tid]) - __ldg(&mu_p[node*16 + tid]);

        out[node*16 + tid]            = g + ALPHA * dm / sp;
        out[NODES*K_ + node*16 + tid] = ALPHA * 0.5f * (1.0f / sp - 1.0f / sq);
    }
}

extern "C" void kernel_launch(void* const* d_in, const int* in_sizes, int n_in,
                              void* d_out, int out_size)
{
    const float* mu_q    = (const float*)d_in[0];
    const float* sigma_q = (const float*)d_in[1];
    const float* mu_p    = (const float*)d_in[2];
    const float* sigma_p = (const float*)d_in[3];
    const float* beta    = (const float*)d_in[4];
    const float* phi     = (const float*)d_in[5];
    const float* gen     = (const float*)d_in[6];
    float* out = (float*)d_out;

    prep_kernel<<<NODES / WPB, 128>>>(mu_q, sigma_q, phi, gen);
    pair_kernel<<<NODES, 256>>>(mu_q, sigma_q, mu_p, sigma_p, beta, out);
}

// round 8
// speedup vs baseline: 1.2560x; 1.0964x over previous
#include <cuda_runtime.h>
#include <cuda_bf16.h>
#include <math.h>

// Problem constants
#define B_    8
#define N_    128
#define K_    16
#define ALPHA 0.01f
#define LAM   1.0f
#define KAPPA 1.0f
#define EPS   1e-6f

#define NODES (B_ * N_)   // 1024
#define WPB   4           // warps (nodes) per block in prep

// Scratch (device globals — no allocation allowed)
// M_g layout per node: [l4][k][c] so float4 idx (node*64 + l4*16 + k) is lane-coalesced.
__device__ __align__(16) float E_g[NODES * K_ * K_];
__device__ __align__(16) float M_g[NODES * K_ * K_];
__device__ __align__(16) float u_g[NODES * K_];
__device__ __align__(16) float t_g[NODES * K_];   // t_j = M_j u_j
__device__ __align__(16) float c_g[NODES];        // c_j = u_j . t_j

// ---------------------------------------------------------------------------
// Warp-cooperative 16x16 matmul: D = S1 * S2 (+ acc init), row-major smem.
// Lane owns row r = lane>>1, cols cb..cb+7 (cb = (lane&1)*8).
// ---------------------------------------------------------------------------
__device__ __forceinline__ void warp_mm(const float* __restrict__ S1,
                                        const float* __restrict__ S2,
                                        float* __restrict__ D,
                                        int r, int cb, float* acc)
{
    float row[16];
    {
        const float4* rp = (const float4*)(S1 + r * 16);
        float4 r0 = rp[0], r1 = rp[1], r2 = rp[2], r3 = rp[3];
        row[0]=r0.x; row[1]=r0.y; row[2]=r0.z; row[3]=r0.w;
        row[4]=r1.x; row[5]=r1.y; row[6]=r1.z; row[7]=r1.w;
        row[8]=r2.x; row[9]=r2.y; row[10]=r2.z; row[11]=r2.w;
        row[12]=r3.x; row[13]=r3.y; row[14]=r3.z; row[15]=r3.w;
    }
    #pragma unroll
    for (int l = 0; l < 16; l++) {
        const float4 b0 = *(const float4*)(S2 + l*16 + cb);
        const float4 b1 = *(const float4*)(S2 + l*16 + cb + 4);
        acc[0] = fmaf(row[l], b0.x, acc[0]);
        acc[1] = fmaf(row[l], b0.y, acc[1]);
        acc[2] = fmaf(row[l], b0.z, acc[2]);
        acc[3] = fmaf(row[l], b0.w, acc[3]);
        acc[4] = fmaf(row[l], b1.x, acc[4]);
        acc[5] = fmaf(row[l], b1.y, acc[5]);
        acc[6] = fmaf(row[l], b1.z, acc[6]);
        acc[7] = fmaf(row[l], b1.w, acc[7]);
    }
    *(float4*)(D + r*16 + cb)     = make_float4(acc[0], acc[1], acc[2], acc[3]);
    *(float4*)(D + r*16 + cb + 4) = make_float4(acc[4], acc[5], acc[6], acc[7]);
    __syncwarp();
}

// ---------------------------------------------------------------------------
// Kernel 1: warp-per-node expm precompute (no block barriers).
// Outputs E, M = E^T D^{-1} E (permuted), u = E^T mu, t = M u, c = u.t
// ---------------------------------------------------------------------------
__global__ __launch_bounds__(128)
void prep_kernel(const float* __restrict__ mu_q,
                 const float* __restrict__ sigma_q,
                 const float* __restrict__ phi,
                 const float* __restrict__ gen)
{
    const int lane = threadIdx.x & 31;
    const int wrp  = threadIdx.x >> 5;
    const int node = blockIdx.x * WPB + wrp;
    const int r    = lane >> 1;
    const int cb   = (lane & 1) * 8;

    __shared__ __align__(16) float sm[WPB * 832];
    float* P0 = sm + wrp * 832;     // A
    float* P1 = P0 + 256;           // slot 1
    float* P2 = P0 + 512;           // slot 2
    float* dv = P0 + 768;           // dinv[16]
    float* mh = P0 + 784;           // mu[16]
    float* um = P0 + 800;           // u[16]
    float* tm = P0 + 816;           // t[16]

    // ---- build A ----
    const float q0 = __ldg(&phi[node*3 + 0]);
    const float q1 = __ldg(&phi[node*3 + 1]);
    const float q2 = __ldg(&phi[node*3 + 2]);
    const int gi = r * 16 + cb;
    float a[8];
    {
        const float4 g00 = __ldg((const float4*)(gen + gi));
        const float4 g01 = __ldg((const float4*)(gen + gi + 4));
        const float4 g10 = __ldg((const float4*)(gen + 256 + gi));
        const float4 g11 = __ldg((const float4*)(gen + 256 + gi + 4));
        const float4 g20 = __ldg((const float4*)(gen + 512 + gi));
        const float4 g21 = __ldg((const float4*)(gen + 512 + gi + 4));
        a[0] = q0*g00.x + q1*g10.x + q2*g20.x;
        a[1] = q0*g00.y + q1*g10.y + q2*g20.y;
        a[2] = q0*g00.z + q1*g10.z + q2*g20.z;
        a[3] = q0*g00.w + q1*g10.w + q2*g20.w;
        a[4] = q0*g01.x + q1*g11.x + q2*g21.x;
        a[5] = q0*g01.y + q1*g11.y + q2*g21.y;
        a[6] = q0*g01.z + q1*g11.z + q2*g21.z;
        a[7] = q0*g01.w + q1*g11.w + q2*g21.w;
    }

    // ---- inf-norm via shfl ----
    float s = fabsf(a[0]) + fabsf(a[1]) + fabsf(a[2]) + fabsf(a[3])
            + fabsf(a[4]) + fabsf(a[5]) + fabsf(a[6]) + fabsf(a[7]);
    s += __shfl_xor_sync(0xffffffffu, s, 1);
    float mx = s;
    mx = fmaxf(mx, __shfl_xor_sync(0xffffffffu, mx, 2));
    mx = fmaxf(mx, __shfl_xor_sync(0xffffffffu, mx, 4));
    mx = fmaxf(mx, __shfl_xor_sync(0xffffffffu, mx, 8));
    mx = fmaxf(mx, __shfl_xor_sync(0xffffffffu, mx, 16));
    int s_sq = 0;
    while (mx > 1.0f && s_sq < 30) { mx *= 0.5f; s_sq++; }
    const float sc = ldexpf(1.0f, -s_sq);
    #pragma unroll
    for (int e = 0; e < 8; e++) a[e] *= sc;
    *(float4*)(P0 + r*16 + cb)     = make_float4(a[0], a[1], a[2], a[3]);
    *(float4*)(P0 + r*16 + cb + 4) = make_float4(a[4], a[5], a[6], a[7]);
    if (lane < 16) {
        const float sq = fmaxf(__ldg(&sigma_q[node*16 + lane]), EPS);
        dv[lane] = 1.0f / (sq + EPS);
        mh[lane] = __ldg(&mu_q[node*16 + lane]);
    }
    __syncwarp();

    // ---- A2 -> P1, A4 -> P2 ----
    float a2own[8] = {0,0,0,0,0,0,0,0};
    warp_mm(P0, P0, P1, r, cb, a2own);
    float a4own[8] = {0,0,0,0,0,0,0,0};
    warp_mm(P1, P1, P2, r, cb, a4own);

    // ---- tails ----
    float even[8], odd[8];
    {
        float row[16];
        {
            const float4* rp = (const float4*)(P2 + r * 16);
            float4 r0 = rp[0], r1 = rp[1], r2 = rp[2], r3 = rp[3];
            row[0]=r0.x; row[1]=r0.y; row[2]=r0.z; row[3]=r0.w;
            row[4]=r1.x; row[5]=r1.y; row[6]=r1.z; row[7]=r1.w;
            row[8]=r2.x; row[9]=r2.y; row[10]=r2.z; row[11]=r2.w;
            row[12]=r3.x; row[13]=r3.y; row[14]=r3.z; row[15]=r3.w;
        }
        float S2e[8] = {0,0,0,0,0,0,0,0};
        float S4e[8] = {0,0,0,0,0,0,0,0};
        #pragma unroll
        for (int l = 0; l < 16; l++) {
            const float4 b0 = *(const float4*)(P1 + l*16 + cb);
            const float4 b1 = *(const float4*)(P1 + l*16 + cb + 4);
            const float4 d0 = *(const float4*)(P2 + l*16 + cb);
            const float4 d1 = *(const float4*)(P2 + l*16 + cb + 4);
            S2e[0]=fmaf(row[l],b0.x,S2e[0]); S2e[1]=fmaf(row[l],b0.y,S2e[1]);
            S2e[2]=fmaf(row[l],b0.z,S2e[2]); S2e[3]=fmaf(row[l],b0.w,S2e[3]);
            S2e[4]=fmaf(row[l],b1.x,S2e[4]); S2e[5]=fmaf(row[l],b1.y,S2e[5]);
            S2e[6]=fmaf(row[l],b1.z,S2e[6]); S2e[7]=fmaf(row[l],b1.w,S2e[7]);
            S4e[0]=fmaf(row[l],d0.x,S4e[0]); S4e[1]=fmaf(row[l],d0.y,S4e[1]);
            S4e[2]=fmaf(row[l],d0.z,S4e[2]); S4e[3]=fmaf(row[l],d0.w,S4e[3]);
            S4e[4]=fmaf(row[l],d1.x,S4e[4]); S4e[5]=fmaf(row[l],d1.y,S4e[5]);
            S4e[6]=fmaf(row[l],d1.z,S4e[6]); S4e[7]=fmaf(row[l],d1.w,S4e[7]);
        }
        #pragma unroll
        for (int e = 0; e < 8; e++) {
            const float idn = (r == cb + e) ? 1.0f : 0.0f;
            even[e] = idn + 0.5f        * a2own[e] + (1.0f/24.0f)  * a4own[e]
                          + (1.0f/720.0f)  * S2e[e] + (1.0f/40320.0f)  * S4e[e];
            odd[e]  = idn + (1.0f/6.0f) * a2own[e] + (1.0f/120.0f) * a4own[e]
                          + (1.0f/5040.0f) * S2e[e] + (1.0f/362880.0f) * S4e[e];
        }
    }
    __syncwarp();
    *(float4*)(P1 + r*16 + cb)     = make_float4(odd[0], odd[1], odd[2], odd[3]);
    *(float4*)(P1 + r*16 + cb + 4) = make_float4(odd[4], odd[5], odd[6], odd[7]);
    __syncwarp();

    // ---- E = even + A * odd -> P2 ----
    warp_mm(P0, P1, P2, r, cb, even);

    // ---- squarings ----
    float* Xp = P2;
    float* Yp = P1;
    for (int t = 0; t < s_sq; t++) {
        float acc[8] = {0,0,0,0,0,0,0,0};
        warp_mm(Xp, Xp, Yp, r, cb, acc);
        float* tmp = Xp; Xp = Yp; Yp = tmp;
    }
    // Xp holds E (row-major).

    // ---- u[k] = col k of E . mu ----
    if (lane < 16) {
        float uu = 0.f;
        #pragma unroll
        for (int l = 0; l < 16; l++) uu = fmaf(Xp[l*16 + lane], mh[l], uu);
        um[lane] = uu;
        u_g[node*16 + lane] = uu;
    }
    __syncwarp();

    // ---- M[r][cb+e] = sum_l E[l][r] dinv[l] E[l][cb+e];  t = M u;  c = u.t ----
    {
        float colr[16];
        #pragma unroll
        for (int l = 0; l < 16; l++) colr[l] = Xp[l*16 + r] * dv[l];
        float m[8] = {0,0,0,0,0,0,0,0};
        #pragma unroll
        for (int l = 0; l < 16; l++) {
            const float4 e0 = *(const float4*)(Xp + l*16 + cb);
            const float4 e1 = *(const float4*)(Xp + l*16 + cb + 4);
            m[0]=fmaf(colr[l],e0.x,m[0]); m[1]=fmaf(colr[l],e0.y,m[1]);
            m[2]=fmaf(colr[l],e0.z,m[2]); m[3]=fmaf(colr[l],e0.w,m[3]);
            m[4]=fmaf(colr[l],e1.x,m[4]); m[5]=fmaf(colr[l],e1.y,m[5]);
            m[6]=fmaf(colr[l],e1.z,m[6]); m[7]=fmaf(colr[l],e1.w,m[7]);
        }
        float* Md = M_g + node*256;
        *(float4*)(Md + (cb >> 2)*64       + r*4) = make_float4(m[0], m[1], m[2], m[3]);
        *(float4*)(Md + ((cb >> 2) + 1)*64 + r*4) = make_float4(m[4], m[5], m[6], m[7]);
        const float4 e0 = *(const float4*)(Xp + r*16 + cb);
        const float4 e1 = *(const float4*)(Xp + r*16 + cb + 4);
        *(float4*)(E_g + node*256 + r*16 + cb)     = e0;
        *(float4*)(E_g + node*256 + r*16 + cb + 4) = e1;

        // t_r = M[r][:] . u  (combine the two half-rows via shfl)
        float tp = 0.f;
        #pragma unroll
        for (int e = 0; e < 8; e++) tp = fmaf(m[e], um[cb + e], tp);
        tp += __shfl_xor_sync(0xffffffffu, tp, 1);
        if ((lane & 1) == 0) {
            tm[r] = tp;
            t_g[node*16 + r] = tp;
        }
    }
    __syncwarp();
    // c = u . t  (reduce over 16 rows; lanes 16-31 mirror lanes 0-15)
    {
        float pc = um[lane & 15] * tm[lane & 15];
        pc += __shfl_xor_sync(0xffffffffu, pc, 1);
        pc += __shfl_xor_sync(0xffffffffu, pc, 2);
        pc += __shfl_xor_sync(0xffffffffu, pc, 4);
        pc += __shfl_xor_sync(0xffffffffu, pc, 8);
        if (lane == 0) c_g[node] = pc;
    }
}

// ---------------------------------------------------------------------------
// Kernel 2: pair reduction using precomputed t_j, c_j.
// One block per (b,i): 256 threads = 16 half-warps, 8 iterations over j.
//   a_k = (M_j u_i)_k ; v_k = a_k - t_jk
//   kl  = 0.5 u_i.a - u_i.t_j + 0.5 c_j = shfl16( u_ik(0.5a_k - t_jk) ) + 0.5c_j
// ---------------------------------------------------------------------------
__global__ __launch_bounds__(256, 4)
void pair_kernel(const float* __restrict__ mu_q,
                 const float* __restrict__ sigma_q,
                 const float* __restrict__ mu_p,
                 const float* __restrict__ sigma_p,
                 const float* __restrict__ beta,
                 float* __restrict__ out)
{
    const int blk = blockIdx.x;        // 0..1023
    const int b   = blk >> 7;
    const int i   = blk & 127;
    const int tid = threadIdx.x;       // 0..255

    __shared__ __align__(16) float t_sh[N_ * K_];     // 8 KB
    __shared__ float us[16];
    __shared__ float c_sh[N_];
    __shared__ float beta_sh[N_];
    __shared__ float red1[16][16];
    __shared__ float red2[16][16];
    __shared__ float red3[16];
    __shared__ float tvec[16];

    float4* t4 = (float4*)t_sh;
    const float4* tg4 = (const float4*)(t_g + b * N_ * K_);
    #pragma unroll
    for (int idx = tid; idx < N_ * K_ / 4; idx += 256) t4[idx] = tg4[idx];
    if (tid < N_) {
        c_sh[tid]    = c_g[b * N_ + tid];
        beta_sh[tid] = __ldg(&beta[(b * N_ + i) * N_ + tid]);
    }
    if (tid < 16) us[tid] = u_g[(b * N_ + i) * 16 + tid];
    __syncthreads();

    const int k  = tid & 15;           // component / row
    const int hw = tid >> 4;           // half-warp id 0..15

    float uir[16];
    {
        const float4* p = (const float4*)us;
        float4 v0 = p[0], v1 = p[1], v2 = p[2], v3 = p[3];
        uir[0]=v0.x;  uir[1]=v0.y;  uir[2]=v0.z;  uir[3]=v0.w;
        uir[4]=v1.x;  uir[5]=v1.y;  uir[6]=v1.z;  uir[7]=v1.w;
        uir[8]=v2.x;  uir[9]=v2.y;  uir[10]=v2.z; uir[11]=v2.w;
        uir[12]=v3.x; uir[13]=v3.y; uir[14]=v3.z; uir[15]=v3.w;
    }
    const float ui_k = us[k];

    float s1 = 0.f, s2 = 0.f, s3 = 0.f;
    const float4* Mb4 = (const float4*)(M_g + b * N_ * 256);

    #pragma unroll 2
    for (int iter = 0; iter < 8; iter++) {
        const int j = iter * 16 + hw;
        const float4* Mj = Mb4 + j * 64;

        const float4 m0 = __ldg(&Mj[ 0 + k]);
        const float4 m1 = __ldg(&Mj[16 + k]);
        const float4 m2 = __ldg(&Mj[32 + k]);
        const float4 m3 = __ldg(&Mj[48 + k]);

        float aa = m0.x * uir[0];
        aa = fmaf(m0.y, uir[1],  aa); aa = fmaf(m0.z, uir[2],  aa); aa = fmaf(m0.w, uir[3],  aa);
        aa = fmaf(m1.x, uir[4],  aa); aa = fmaf(m1.y, uir[5],  aa); aa = fmaf(m1.z, uir[6],  aa); aa = fmaf(m1.w, uir[7],  aa);
        aa = fmaf(m2.x, uir[8],  aa); aa = fmaf(m2.y, uir[9],  aa); aa = fmaf(m2.z, uir[10], aa); aa = fmaf(m2.w, uir[11], aa);
        aa = fmaf(m3.x, uir[12], aa); aa = fmaf(m3.y, uir[13], aa); aa = fmaf(m3.z, uir[14], aa); aa = fmaf(m3.w, uir[15], aa);

        const float tjk = t_sh[j*16 + k];
        const float v   = aa - tjk;
        float p = ui_k * fmaf(0.5f, aa, -tjk);
        p += __shfl_xor_sync(0xffffffffu, p, 8);
        p += __shfl_xor_sync(0xffffffffu, p, 4);
        p += __shfl_xor_sync(0xffffffffu, p, 2);
        p += __shfl_xor_sync(0xffffffffu, p, 1);
        const float kl = p + 0.5f * c_sh[j];

        const float bj  = beta_sh[j];
        const float bkl = bj * kl;
        s1 = fmaf(bj,  v, s1);
        s2 = fmaf(bkl, v, s2);
        s3 += bkl;
    }

    red1[hw][k] = s1;
    red2[hw][k] = s2;
    if (k == 0) red3[hw] = s3;
    __syncthreads();

    if (tid < 16) {
        float S1 = 0.f, S2 = 0.f, S3 = 0.f;
        #pragma unroll
        for (int h = 0; h < 16; h++) {
            S1 += red1[h][tid];
            S2 += red2[h][tid];
            S3 += red3[h];
        }
        tvec[tid] = LAM * S1 + (LAM / KAPPA) * (S2 - S3 * S1);
    }
    __syncthreads();

    if (tid < 16) {
        const int node = b * N_ + i;
        const float* Ei = E_g + node * 256;
        float g = 0.f;
        #pragma unroll
        for (int l = 0; l < 16; l++) g = fmaf(Ei[tid*16 + l], tvec[l], g);

        const float sp = fmaxf(__ldg(&sigma_p[node*16 + tid]), EPS);
        const float sq = fmaxf(__ldg(&sigma_q[node*16 + tid]), EPS);
        const float dm = __ldg(&mu_q[node*16 + tid]) - __ldg(&mu_p[node*16 + tid]);

        out[node*16 + tid]            = g + ALPHA * dm / sp;
        out[NODES*K_ + node*16 + tid] = ALPHA * 0.5f * (1.0f / sp - 1.0f / sq);
    }
}

extern "C" void kernel_launch(void* const* d_in, const int* in_sizes, int n_in,
                              void* d_out, int out_size)
{
    const float* mu_q    = (const float*)d_in[0];
    const float* sigma_q = (const float*)d_in[1];
    const float* mu_p    = (const float*)d_in[2];
    const float* sigma_p = (const float*)d_in[3];
    const float* beta    = (const float*)d_in[4];
    const float* phi     = (const float*)d_in[5];
    const float* gen     = (const float*)d_in[6];
    float* out = (float*)d_out;

    prep_kernel<<<NODES / WPB, 128>>>(mu_q, sigma_q, phi, gen);
    pair_kernel<<<NODES, 256>>>(mu_q, sigma_q, mu_p, sigma_p, beta, out);
}